// round 13
// baseline (speedup 1.0000x reference)
#include <cuda_runtime.h>
#include <math.h>

// B=1024, NL=64, W=2048; inner scan = 62 layers.
#define TMM_B  1024
#define TMM_NL 64
#define TMM_W  2048
#define TMM_NI 62
#define TWO_PI 6.283185307179586f
#define EPS_N  1e-8f
#define EPS_Y  1e-9f

// R11: the hidden saturated pipe is SFU (__sincosf ~= 3 SFU ops @ rt 8 ->
// 24 cyc/output/layer = exactly the 23-24.6 cyc plateau of R5/R8/R9).
// Rebalance: ~1/6 of all sincos (chain b, layers i%3==0) computed via a
// packed-f32x2 FMA-pipe polynomial (Cody-Waite pi/2 reduction, q<=6,
// joint sin+cos Horner). Removes 24 SFU-cyc for +18 FMA-cyc on those
// layers -> both pipes land at ~20 cyc/output.

typedef unsigned long long u64;

__device__ __forceinline__ u64 pk2(float lo, float hi) {
    u64 r; asm("mov.b64 %0, {%1, %2};" : "=l"(r) : "f"(lo), "f"(hi)); return r;
}
__device__ __forceinline__ void upk2(u64 v, float& lo, float& hi) {
    asm("mov.b64 {%0, %1}, %2;" : "=f"(lo), "=f"(hi) : "l"(v));
}
__device__ __forceinline__ u64 mul2(u64 a, u64 b) {
    u64 r; asm("mul.rn.f32x2 %0, %1, %2;" : "=l"(r) : "l"(a), "l"(b)); return r;
}
__device__ __forceinline__ u64 fma2(u64 a, u64 b, u64 c) {
    u64 r; asm("fma.rn.f32x2 %0, %1, %2, %3;" : "=l"(r) : "l"(a), "l"(b), "l"(c)); return r;
}

#define RND_MAGIC 12582912.0f          // 1.5 * 2^23
#define TWO_OPI   0.636619772f
#define PIO2_HI   1.57079637e+0f       // nearest-float pi/2
#define PIO2_LO  -4.37113883e-8f       // pi/2 - PIO2_HI

// sin/cos of phi in [0, ~8.7] via pi/2 reduction + packed Horner.
// qf must equal rint(phi * 2/pi) as an exact-integer float.
__device__ __forceinline__ void sincos_poly(float phi, float qf, float& s, float& c)
{
    float r = fmaf(-qf, PIO2_HI, phi);
    r       = fmaf(-qf, PIO2_LO, r);          // r in [-pi/4, pi/4]
    const float x = r * r;

    const u64 xx  = pk2(x, x);
    const u64 K3  = pk2(-1.9841270e-4f, -1.3888889e-3f);  // (S3, C3)
    const u64 K2  = pk2( 8.3333338e-3f,  4.1666668e-2f);  // (S2, C2)
    const u64 K1  = pk2(-1.6666667e-1f, -5.0000000e-1f);  // (S1, C1)
    const u64 K0  = pk2( 1.0f,           1.0f);
    u64 t = fma2(K3, xx, K2);
    t     = fma2(t,  xx, K1);
    t     = fma2(t,  xx, K0);
    const u64 sc = mul2(t, pk2(r, 1.0f));     // (sin r, cos r)

    float sr, cr;
    upk2(sc, sr, cr);

    const int qi = (int)qf;                   // exact, nonnegative
    const bool swap = (qi & 1);
    const unsigned sgn_s = (unsigned)(qi & 2) << 30;         // sin<0: q mod 4 in {2,3}
    const unsigned sgn_c = (unsigned)((qi + 1) & 2) << 30;   // cos<0: q mod 4 in {1,2}

    const float sv = swap ? cr : sr;
    const float cv = swap ? sr : cr;
    s = __uint_as_float(__float_as_uint(sv) ^ sgn_s);
    c = __uint_as_float(__float_as_uint(cv) ^ sgn_c);
}

__device__ __forceinline__ void upd(u64& P, u64& Q, float s, float c,
                                    u64 nmn, u64 miv)
{
    const u64 ss = pk2(s, s);
    const u64 cc = pk2(c, c);
    const u64 u  = mul2(ss, nmn);   // (n*s, -n*s)
    const u64 v  = mul2(ss, miv);   // (-s/(n+e), +s/(n+e))
    const u64 t1 = mul2(Q, u);
    const u64 t2 = mul2(P, v);
    P = fma2(P, cc, t1);
    Q = fma2(Q, cc, t2);
}

__device__ __forceinline__ float tmm_epilogue(float A, float C, float Bv, float D,
                                              float nin, float nsub)
{
    const float Ae = A + EPS_Y;
    const float t1 = nin * Ae;
    const float t2 = D * nsub;
    const float t3 = nin * Bv * nsub;
    const float nr = t1 - t2;
    const float ni = t3 - C;
    const float dr = t1 + t2;
    const float di = t3 + C;
    return fmaf(nr, nr, ni * ni) / fmaf(dr, dr, di * di);
}

__global__ __launch_bounds__(256, 2)
void tmm_kernel(const float* __restrict__ n_layers,
                const float* __restrict__ d_layers,
                const float* __restrict__ wavelengths,
                float* __restrict__ out)
{
    __shared__ float  s_nd   [TMM_NI];   // n*d
    __shared__ float  s_nd2op[TMM_NI];   // n*d * 2/pi
    __shared__ float4 s_q    [TMM_NI];   // {n, -n, -1/(n+e), +1/(n+e)}
    __shared__ float  s_end[2];          // n_in, n_sub

    const int b  = blockIdx.y;
    const int w0 = blockIdx.x * blockDim.x + threadIdx.x;   // 0..1023
    const int w1 = w0 + (TMM_W / 2);                        // 1024..2047

    const float* nrow = n_layers + (size_t)b * TMM_NL;
    const float* drow = d_layers + (size_t)b * TMM_NL;

    for (int i = threadIdx.x; i < TMM_NI; i += blockDim.x) {
        float ni  = nrow[i + 1];
        float di  = drow[i + 1];
        float inv = 1.0f / (ni + EPS_N);
        float nd  = ni * di;
        s_nd   [i] = nd;
        s_nd2op[i] = nd * TWO_OPI;
        s_q    [i] = make_float4(ni, -ni, -inv, inv);
    }
    if (threadIdx.x == 0) {
        s_end[0] = nrow[0];
        s_end[1] = nrow[TMM_NL - 1];
    }
    __syncthreads();

    const float k0a = TWO_PI / wavelengths[w0];
    const float k0b = TWO_PI / wavelengths[w1];

    u64 P0 = pk2(1.0f, 0.0f);   // (A, C)  chain 0
    u64 Q0 = pk2(0.0f, 1.0f);   // (Bv, D) chain 0
    u64 P1 = pk2(1.0f, 0.0f);   // chain 1
    u64 Q1 = pk2(0.0f, 1.0f);

    // MUFU-only layer for both chains.
    auto layer_mufu = [&](int i) {
        const float nd = s_nd[i];
        const float4 q = s_q[i];
        const u64 nmn = pk2(q.x, q.y);
        const u64 miv = pk2(q.z, q.w);
        float sa, ca, sb, cb;
        __sincosf(nd * k0a, &sa, &ca);
        __sincosf(nd * k0b, &sb, &cb);
        upd(P0, Q0, sa, ca, nmn, miv);
        upd(P1, Q1, sb, cb, nmn, miv);
    };
    // Mixed layer: chain a MUFU, chain b polynomial (FMA pipe).
    auto layer_mix = [&](int i) {
        const float nd = s_nd[i];
        const float4 q = s_q[i];
        const u64 nmn = pk2(q.x, q.y);
        const u64 miv = pk2(q.z, q.w);
        float sa, ca, sb, cb;
        __sincosf(nd * k0a, &sa, &ca);
        const float qf = fmaf(s_nd2op[i], k0b, RND_MAGIC) - RND_MAGIC;
        sincos_poly(nd * k0b, qf, sb, cb);
        upd(P0, Q0, sa, ca, nmn, miv);
        upd(P1, Q1, sb, cb, nmn, miv);
    };

    // 20 triples: {mix, mufu, mufu}; tail = layers 60 (mix), 61 (mufu).
    #pragma unroll 2
    for (int t = 0; t < 20; t++) {
        const int i = t * 3;
        layer_mix (i);
        layer_mufu(i + 1);
        layer_mufu(i + 2);
    }
    layer_mix (60);
    layer_mufu(61);

    const float nin  = s_end[0];
    const float nsub = s_end[1];

    float A, C, Bv, D;
    upk2(P0, A, C); upk2(Q0, Bv, D);
    const float R0 = tmm_epilogue(A, C, Bv, D, nin, nsub);
    upk2(P1, A, C); upk2(Q1, Bv, D);
    const float R1 = tmm_epilogue(A, C, Bv, D, nin, nsub);

    float* orow = out + (size_t)b * TMM_W;
    orow[w0] = R0;
    orow[w1] = R1;
}

extern "C" void kernel_launch(void* const* d_in, const int* in_sizes, int n_in,
                              void* d_out, int out_size)
{
    const float* n_layers    = (const float*)d_in[0];
    const float* d_layers    = (const float*)d_in[1];
    const float* wavelengths = (const float*)d_in[2];
    float* out = (float*)d_out;

    dim3 block(256);
    dim3 grid((TMM_W / 2) / 256, TMM_B);   // (4, 1024)
    tmm_kernel<<<grid, block>>>(n_layers, d_layers, wavelengths, out);
}

// round 15
// speedup vs baseline: 1.1810x; 1.1810x over previous
#include <cuda_runtime.h>
#include <math.h>

// B=1024, NL=64, W=2048; inner scan = 62 layers.
#define TMM_B   1024
#define TMM_NL  64
#define TMM_W   2048
#define TMM_NI  62
#define TMM_BPB 4          // batches per block
#define TWO_PI  6.283185307179586f
#define EPS_N   1e-8f
#define EPS_Y   1e-9f

// R13: SFU-led regime (MUFU ~80% busy @ ~2.0GHz; floor ~56us).
//  - chain-packed f32x2 accumulators: lanes = the two wavelength chains.
//    With Cn = -C all four updates share one form -> 10 packed ops/layer:
//      ns = s*(n,n); mv = s*(-inv,-inv)
//      A'=fma(Bv,ns,A*c)  Bv'=fma(A,mv,Bv*c)  Cn'=fma(D,ns,Cn*c)  D'=fma(Cn,mv,D*c)
//  - one-layer trig prefetch (peeled last iter, branch-free)
//  - 4 batches/block: one smem fill + sync amortized 4x
//  - no minBlocks reg clamp

typedef unsigned long long u64;

__device__ __forceinline__ u64 pk2(float lo, float hi) {
    u64 r; asm("mov.b64 %0, {%1, %2};" : "=l"(r) : "f"(lo), "f"(hi)); return r;
}
__device__ __forceinline__ void upk2(u64 v, float& lo, float& hi) {
    asm("mov.b64 {%0, %1}, %2;" : "=f"(lo), "=f"(hi) : "l"(v));
}
__device__ __forceinline__ u64 mul2(u64 a, u64 b) {
    u64 r; asm("mul.rn.f32x2 %0, %1, %2;" : "=l"(r) : "l"(a), "l"(b)); return r;
}
__device__ __forceinline__ u64 fma2(u64 a, u64 b, u64 c) {
    u64 r; asm("fma.rn.f32x2 %0, %1, %2, %3;" : "=l"(r) : "l"(a), "l"(b), "l"(c)); return r;
}

__device__ __forceinline__ float tmm_epilogue(float A, float C, float Bv, float D,
                                              float nin, float nsub)
{
    const float Ae = A + EPS_Y;
    const float t1 = nin * Ae;          // Re(n_in*(E+eps))
    const float t2 = D * nsub;          // Re(H)
    const float t3 = nin * Bv * nsub;   // Im(n_in*(E+eps)); Im(H)=C
    const float nr = t1 - t2;
    const float ni = t3 - C;
    const float dr = t1 + t2;
    const float di = t3 + C;
    return fmaf(nr, nr, ni * ni) / fmaf(dr, dr, di * di);
}

__global__ __launch_bounds__(256)
void tmm_kernel(const float* __restrict__ n_layers,
                const float* __restrict__ d_layers,
                const float* __restrict__ wavelengths,
                float* __restrict__ out)
{
    __shared__ float4 s_c[TMM_BPB][TMM_NI];  // {n*d, n, -1/(n+e), 0}
    __shared__ float2 s_e[TMM_BPB];          // {n_in, n_sub}

    const int tid = threadIdx.x;
    const int w0  = blockIdx.x * 256 + tid;     // 0..1023
    const int w1  = w0 + (TMM_W / 2);           // 1024..2047
    const int b0  = blockIdx.y * TMM_BPB;

    for (int idx = tid; idx < TMM_BPB * TMM_NI; idx += 256) {
        const int bb = idx / TMM_NI;
        const int i  = idx % TMM_NI;
        const float* nrow = n_layers + (size_t)(b0 + bb) * TMM_NL;
        const float* drow = d_layers + (size_t)(b0 + bb) * TMM_NL;
        const float ni = nrow[i + 1];
        const float di = drow[i + 1];
        s_c[bb][i] = make_float4(ni * di, ni, -1.0f / (ni + EPS_N), 0.0f);
    }
    if (tid < TMM_BPB) {
        const float* nrow = n_layers + (size_t)(b0 + tid) * TMM_NL;
        s_e[tid] = make_float2(nrow[0], nrow[TMM_NL - 1]);
    }
    __syncthreads();

    const float k0a = TWO_PI / wavelengths[w0];
    const float k0b = TWO_PI / wavelengths[w1];

    #pragma unroll 1
    for (int bb = 0; bb < TMM_BPB; bb++) {
        const float4* q = s_c[bb];

        u64 A  = pk2(1.0f, 1.0f);   // lanes = (chain a, chain b)
        u64 Bv = pk2(0.0f, 0.0f);
        u64 Cn = pk2(0.0f, 0.0f);   // Cn = -C
        u64 D  = pk2(1.0f, 1.0f);

        // Prologue: trig for layer 0 in flight.
        float sa, ca, sb, cb;
        {
            const float nd0 = q[0].x;
            __sincosf(nd0 * k0a, &sa, &ca);
            __sincosf(nd0 * k0b, &sb, &cb);
        }

        #pragma unroll 2
        for (int i = 0; i < TMM_NI - 1; i++) {
            // Prefetch layer i+1 trig (independent of recurrence).
            const float ndn = q[i + 1].x;
            float sa_n, ca_n, sb_n, cb_n;
            __sincosf(ndn * k0a, &sa_n, &ca_n);
            __sincosf(ndn * k0b, &sb_n, &cb_n);

            // Consume layer i.
            const float n_  = q[i].y;
            const float mi_ = q[i].z;
            const u64 sp = pk2(sa, sb);
            const u64 cp = pk2(ca, cb);
            const u64 nn = pk2(n_,  n_);
            const u64 mi = pk2(mi_, mi_);

            const u64 ns = mul2(sp, nn);    // (n*s)   per chain
            const u64 mv = mul2(sp, mi);    // (-s*inv) per chain
            const u64 An = fma2(Bv, ns, mul2(A,  cp));
            const u64 Bn = fma2(A,  mv, mul2(Bv, cp));
            const u64 Cx = fma2(D,  ns, mul2(Cn, cp));
            const u64 Dn = fma2(Cn, mv, mul2(D,  cp));
            A = An; Bv = Bn; Cn = Cx; D = Dn;

            sa = sa_n; ca = ca_n; sb = sb_n; cb = cb_n;
        }
        // Peeled last layer (i = TMM_NI-1).
        {
            const float n_  = q[TMM_NI - 1].y;
            const float mi_ = q[TMM_NI - 1].z;
            const u64 sp = pk2(sa, sb);
            const u64 cp = pk2(ca, cb);
            const u64 nn = pk2(n_,  n_);
            const u64 mi = pk2(mi_, mi_);
            const u64 ns = mul2(sp, nn);
            const u64 mv = mul2(sp, mi);
            const u64 An = fma2(Bv, ns, mul2(A,  cp));
            const u64 Bn = fma2(A,  mv, mul2(Bv, cp));
            const u64 Cx = fma2(D,  ns, mul2(Cn, cp));
            const u64 Dn = fma2(Cn, mv, mul2(D,  cp));
            A = An; Bv = Bn; Cn = Cx; D = Dn;
        }

        const float2 e = s_e[bb];
        float Aa, Ab, Ba, Bb, Ca_, Cb_, Da, Db;
        upk2(A,  Aa, Ab);
        upk2(Bv, Ba, Bb);
        upk2(Cn, Ca_, Cb_);
        upk2(D,  Da, Db);

        const float R0 = tmm_epilogue(Aa, -Ca_, Ba, Da, e.x, e.y);
        const float R1 = tmm_epilogue(Ab, -Cb_, Bb, Db, e.x, e.y);

        float* orow = out + (size_t)(b0 + bb) * TMM_W;
        orow[w0] = R0;
        orow[w1] = R1;
    }
}

extern "C" void kernel_launch(void* const* d_in, const int* in_sizes, int n_in,
                              void* d_out, int out_size)
{
    const float* n_layers    = (const float*)d_in[0];
    const float* d_layers    = (const float*)d_in[1];
    const float* wavelengths = (const float*)d_in[2];
    float* out = (float*)d_out;

    dim3 block(256);
    dim3 grid((TMM_W / 2) / 256, TMM_B / TMM_BPB);   // (4, 256)
    tmm_kernel<<<grid, block>>>(n_layers, d_layers, wavelengths, out);
}